// round 6
// baseline (speedup 1.0000x reference)
#include <cuda_runtime.h>
#include <math.h>

#define T_LEN 480000
#define B_ROWS 64

// RN(1/16000): matches XLA's divide->multiply-by-reciprocal rewrite.
// Load-bearing for correctness (round-4 win) -- do not change.
#define INV_SR 6.25e-5f

// ---------------------------------------------------------------------------
// Branch-free accurate sine -- BIT-IDENTICAL to round-5 version (load-bearing:
// observed Δdelay vs reference is ~0.1 ulp; any sine change risks ~5e-4).
// ---------------------------------------------------------------------------
__device__ __forceinline__ float sin_acc(float x)
{
    const float MAGIC = 12582912.0f;                  // 1.5 * 2^23
    float jf = __fmaf_rn(x, 0.636619747f, MAGIC);     // round(x * 2/pi)
    int   q  = __float_as_int(jf);                    // low bits = quadrant
    float n  = __fsub_rn(jf, MAGIC);

    float r = __fmaf_rn(n, -1.57079601287841796875e+00f, x);
    r = __fmaf_rn(n, -3.13916473738675476075e-07f, r);
    r = __fmaf_rn(n, -5.39030252995776476554e-15f, r);

    float s2 = __fmul_rn(r, r);

    float u = __fmaf_rn(-1.9515295891e-4f, s2,  8.3321608736e-3f);
    u = __fmaf_rn(u, s2, -1.6666654611e-1f);
    float sinr = __fmaf_rn(__fmul_rn(u, s2), r, r);

    float v = __fmaf_rn(2.443315711809948e-5f, s2, -1.388731625493765e-3f);
    v = __fmaf_rn(v, s2, 4.166664568298827e-2f);
    float cosr = __fmaf_rn(__fmul_rn(v, s2), s2, __fmaf_rn(-0.5f, s2, 1.0f));

    float res = (q & 1) ? cosr : sinr;
    unsigned sgn = ((unsigned)q & 2u) << 30;
    return __int_as_float(__float_as_int(res) ^ (int)sgn);
}

// One (i,b) sample. CHECK=false: proven rp>=0 and il>=0 (i >= 800), skip
// clamp + select (-3 instr on 99.8% of work).
template<bool CHECK>
__device__ __forceinline__ float chorus_sample(
    const float* __restrict__ row, int i, float posf, float t, float4 p)
{
    // arg = ((2*pi)*rate) * t -- exact reference f32 op order (p.x = 2pi*rate).
    const float arg = __fmul_rn(p.x, t);
    const float lfo = sin_acc(arg);

    // delay = cds + ((lfo*depth)*cds) -- exact ref rounding order, clip [1,800].
    float delay = __fadd_rn(p.z, __fmul_rn(__fmul_rn(lfo, p.y), p.z));
    delay = fminf(fmaxf(delay, 1.0f), 800.0f);

    const float rp   = __fsub_rn(posf, delay);       // ref's f32 quantization
    const float lowf = floorf(rp);
    const float frac = __fsub_rn(rp, lowf);
    int il = __float2int_rd(rp);
    if (CHECK) il = max(il, 0);

    const float a0 = __ldg(row + il);
    const float a1 = __ldg(row + il + 1);
    const float x  = __ldg(row + i);

    float delayed = __fmaf_rn(frac, __fsub_rn(a1, a0), a0);
    if (CHECK) delayed = (rp >= 0.0f) ? delayed : 0.0f;

    // x*(1-m) + d*m == x + m*(d-x) algebraically; ±1ulp direct, un-amplified.
    return __fmaf_rn(p.w, __fsub_rn(delayed, x), x);
}

template<bool CHECK, bool TWO>
__device__ __forceinline__ void chorus_body(
    const float* __restrict__ audio, float* __restrict__ out,
    const float4* __restrict__ s_p, int i0, int i1)
{
    const float posf0 = (float)i0;
    const float posf1 = (float)i1;
    const float t0 = __fmul_rn(posf0, INV_SR);
    const float t1 = __fmul_rn(posf1, INV_SR);

    const float* row  = audio;
    float*       orow = out;

    #pragma unroll 4
    for (int b = 0; b < B_ROWS; ++b, row += T_LEN, orow += T_LEN) {
        const float4 p = s_p[b];                      // one LDS.128 broadcast
        const float o0 = chorus_sample<CHECK>(row, i0, posf0, t0, p);
        float o1 = 0.0f;
        if (TWO) o1 = chorus_sample<CHECK>(row, i1, posf1, t1, p);
        orow[i0] = o0;
        if (TWO) orow[i1] = o1;
    }
}

__global__ __launch_bounds__(256)
void chorus_kernel(const float* __restrict__ audio,
                   const float* __restrict__ rate_hz,
                   const float* __restrict__ depth,
                   const float* __restrict__ centre_ms,
                   const float* __restrict__ mix,
                   float* __restrict__ out)
{
    __shared__ float4 s_p[B_ROWS];                    // {2pi*rate, depth, cds, mix}

    const float TWO_PI_F = 6.28318530717958647692f;   // f32 = 0x40C90FDB
    if (threadIdx.x < B_ROWS) {
        const int b = threadIdx.x;
        float4 p;
        p.x = __fmul_rn(TWO_PI_F, __ldg(rate_hz + b));
        p.y = __ldg(depth + b);
        p.z = __fmul_rn(__ldg(centre_ms + b), 16.0f);
        p.w = __ldg(mix + b);
        s_p[b] = p;
    }
    __syncthreads();

    const int i0 = blockIdx.x * 512 + threadIdx.x;
    const int i1 = i0 + 256;

    // Block-uniform specialization:
    //  bid >= 2  -> every i >= 1024 > 800 >= delay -> rp >= 0, il >= 0 always.
    //  last block (938th) covers only 256 samples -> TWO=false.
    if (blockIdx.x >= 2) {
        if (i1 < T_LEN) chorus_body<false, true >(audio, out, s_p, i0, i1);
        else            chorus_body<false, false>(audio, out, s_p, i0, i1);
    } else {
        chorus_body<true, true>(audio, out, s_p, i0, i1);
    }
}

extern "C" void kernel_launch(void* const* d_in, const int* in_sizes, int n_in,
                              void* d_out, int out_size)
{
    // metadata order: audio, rate_hz, depth, centre_delay_ms, feedback(unused), mix
    const float* audio     = (const float*)d_in[0];
    const float* rate_hz   = (const float*)d_in[1];
    const float* depth     = (const float*)d_in[2];
    const float* centre_ms = (const float*)d_in[3];
    const float* mix       = (const float*)d_in[5];
    float* out = (float*)d_out;

    (void)in_sizes; (void)n_in; (void)out_size;

    const int threads = 256;
    const int blocks  = (T_LEN + 512 - 1) / 512;      // 938: single wave
    chorus_kernel<<<blocks, threads>>>(audio, rate_hz, depth, centre_ms, mix, out);
}

// round 7
// speedup vs baseline: 1.0561x; 1.0561x over previous
#include <cuda_runtime.h>
#include <math.h>

#define T_LEN 480000
#define B_ROWS 64

// RN(1/16000): matches XLA's divide->multiply-by-reciprocal rewrite.
// Load-bearing for correctness (round-4 win) -- do not change.
#define INV_SR 6.25e-5f

// ---------------------------------------------------------------------------
// Branch-free accurate sine -- BIT-IDENTICAL to rounds 5/6 (load-bearing).
// ---------------------------------------------------------------------------
__device__ __forceinline__ float sin_acc(float x)
{
    const float MAGIC = 12582912.0f;                  // 1.5 * 2^23
    float jf = __fmaf_rn(x, 0.636619747f, MAGIC);     // round(x * 2/pi)
    int   q  = __float_as_int(jf);                    // low bits = quadrant
    float n  = __fsub_rn(jf, MAGIC);

    float r = __fmaf_rn(n, -1.57079601287841796875e+00f, x);
    r = __fmaf_rn(n, -3.13916473738675476075e-07f, r);
    r = __fmaf_rn(n, -5.39030252995776476554e-15f, r);

    float s2 = __fmul_rn(r, r);

    float u = __fmaf_rn(-1.9515295891e-4f, s2,  8.3321608736e-3f);
    u = __fmaf_rn(u, s2, -1.6666654611e-1f);
    float sinr = __fmaf_rn(__fmul_rn(u, s2), r, r);

    float v = __fmaf_rn(2.443315711809948e-5f, s2, -1.388731625493765e-3f);
    v = __fmaf_rn(v, s2, 4.166664568298827e-2f);
    float cosr = __fmaf_rn(__fmul_rn(v, s2), s2, __fmaf_rn(-0.5f, s2, 1.0f));

    float res = (q & 1) ? cosr : sinr;
    unsigned sgn = ((unsigned)q & 2u) << 30;
    return __int_as_float(__float_as_int(res) ^ (int)sgn);
}

// One (i,b) sample. CHECK=false: i >= 1024 > 800 >= delay proves rp >= 0 and
// il >= 0; skip the clamp + select.
template<bool CHECK>
__device__ __forceinline__ float chorus_sample(
    const float* __restrict__ row, int i, float posf, float t, float4 p)
{
    // arg = ((2*pi)*rate) * t -- exact reference f32 op order (p.x = 2pi*rate).
    const float arg = __fmul_rn(p.x, t);
    const float lfo = sin_acc(arg);

    // delay = cds + ((lfo*depth)*cds) -- exact ref rounding order, clip [1,800].
    float delay = __fadd_rn(p.z, __fmul_rn(__fmul_rn(lfo, p.y), p.z));
    delay = fminf(fmaxf(delay, 1.0f), 800.0f);

    const float rp = __fsub_rn(posf, delay);          // ref's f32 quantization
    int il = __float2int_rd(rp);
    if (CHECK) il = max(il, 0);
    const float frac = __fsub_rn(rp, floorf(rp));

    const float a0 = __ldg(row + il);
    const float a1 = __ldg(row + il + 1);
    const float x  = __ldg(row + i);

    float delayed = __fmaf_rn(frac, __fsub_rn(a1, a0), a0);
    if (CHECK) delayed = (rp >= 0.0f) ? delayed : 0.0f;

    // x*(1-m) + d*m == x + m*(d-x); ±1ulp direct error, un-amplified.
    return __fmaf_rn(p.w, __fsub_rn(delayed, x), x);
}

template<bool CHECK>
__device__ __forceinline__ void chorus_body(
    const float* __restrict__ audio, float* __restrict__ out,
    const float4* __restrict__ s_p, int i)
{
    const float posf = (float)i;                      // exact (i < 2^24)
    const float t = __fmul_rn(posf, INV_SR);          // XLA reciprocal-mul

    const float* row  = audio;
    float*       orow = out;

    #pragma unroll 8
    for (int b = 0; b < B_ROWS; ++b, row += T_LEN, orow += T_LEN) {
        const float4 p = s_p[b];                      // one LDS.128 broadcast
        orow[i] = chorus_sample<CHECK>(row, i, posf, t, p);
    }
}

__global__ __launch_bounds__(256)
void chorus_kernel(const float* __restrict__ audio,
                   const float* __restrict__ rate_hz,
                   const float* __restrict__ depth,
                   const float* __restrict__ centre_ms,
                   const float* __restrict__ mix,
                   float* __restrict__ out)
{
    __shared__ float4 s_p[B_ROWS];                    // {2pi*rate, depth, cds, mix}

    const float TWO_PI_F = 6.28318530717958647692f;   // f32 = 0x40C90FDB
    if (threadIdx.x < B_ROWS) {
        const int b = threadIdx.x;
        float4 p;
        p.x = __fmul_rn(TWO_PI_F, __ldg(rate_hz + b));
        p.y = __ldg(depth + b);
        p.z = __fmul_rn(__ldg(centre_ms + b), 16.0f);
        p.w = __ldg(mix + b);
        s_p[b] = p;
    }
    __syncthreads();

    const int i = blockIdx.x * blockDim.x + threadIdx.x;
    if (i >= T_LEN) return;

    // Block-uniform specialization: bid >= 4 -> i >= 1024 -> rp, il in range.
    if (blockIdx.x >= 4) chorus_body<false>(audio, out, s_p, i);
    else                 chorus_body<true >(audio, out, s_p, i);
}

extern "C" void kernel_launch(void* const* d_in, const int* in_sizes, int n_in,
                              void* d_out, int out_size)
{
    // metadata order: audio, rate_hz, depth, centre_delay_ms, feedback(unused), mix
    const float* audio     = (const float*)d_in[0];
    const float* rate_hz   = (const float*)d_in[1];
    const float* depth     = (const float*)d_in[2];
    const float* centre_ms = (const float*)d_in[3];
    const float* mix       = (const float*)d_in[5];
    float* out = (float*)d_out;

    (void)in_sizes; (void)n_in; (void)out_size;

    const int threads = 256;
    const int blocks  = (T_LEN + threads - 1) / threads;   // 1875
    chorus_kernel<<<blocks, threads>>>(audio, rate_hz, depth, centre_ms, mix, out);
}